// round 16
// baseline (speedup 1.0000x reference)
#include <cuda_runtime.h>
#include <cuda_fp16.h>
#include <cstdint>
#include <cstddef>

#define NTOK 8192
#define HDIM 1024
#define NEXP 8
#define TOPK 2
#define IDIM 1024
#define SHI  2048
#define CAP  2560   // ceil(1.25 * 8192 * 2 / 8)

// ---------------- device scratch ----------------
__device__ int   g_topk_idx[NTOK * TOPK];
__device__ float g_topk_w[NTOK * TOPK];
__device__ int   g_etok[NEXP * CAP];
__device__ float g_ewt[NEXP * CAP];
__device__ int   g_counts[NEXP];

// all GEMM operands single fp16
__device__ __align__(128) __half g_x[NTOK * HDIM];
__device__ __align__(128) __half g_wg[NEXP * IDIM * HDIM];
__device__ __align__(128) __half g_wu[NEXP * IDIM * HDIM];
__device__ __align__(128) __half g_wd[NEXP * HDIM * IDIM];
__device__ __align__(128) __half g_sg[SHI * HDIM];
__device__ __align__(128) __half g_su[SHI * HDIM];
__device__ __align__(128) __half g_sd[HDIM * SHI];
__device__ __align__(128) __half g_ar[(size_t)NEXP * CAP * IDIM];
__device__ __align__(128) __half g_as[(size_t)NTOK * SHI];

__device__ __forceinline__ float silu_f(float x) { return x / (1.f + __expf(-x)); }
__device__ __forceinline__ uint32_t sw128(uint32_t b) { return b ^ ((b >> 3) & 0x70); }

__device__ __forceinline__ void cp16(uint32_t dst, const void* src) {
    asm volatile("cp.async.cg.shared.global [%0], [%1], 16;" :: "r"(dst), "l"(src));
}
#define CP_COMMIT() asm volatile("cp.async.commit_group;")
#define CP_WAIT1()  asm volatile("cp.async.wait_group 1;")
#define CP_WAIT0()  asm volatile("cp.async.wait_group 0;")

__device__ __forceinline__ void ldsm4(uint32_t* r, uint32_t addr) {
    asm volatile("ldmatrix.sync.aligned.m8n8.x4.shared.b16 {%0,%1,%2,%3}, [%4];"
                 : "=r"(r[0]), "=r"(r[1]), "=r"(r[2]), "=r"(r[3]) : "r"(addr));
}

__device__ __forceinline__ void mma_f16(float (&c)[4], const uint32_t (&a)[4],
                                        uint32_t b0, uint32_t b1)
{
    asm volatile(
        "mma.sync.aligned.m16n8k16.row.col.f32.f16.f16.f32 "
        "{%0,%1,%2,%3}, {%4,%5,%6,%7}, {%8,%9}, {%0,%1,%2,%3};\n"
        : "+f"(c[0]), "+f"(c[1]), "+f"(c[2]), "+f"(c[3])
        : "r"(a[0]), "r"(a[1]), "r"(a[2]), "r"(a[3]), "r"(b0), "r"(b1));
}

// ---------------- fused fp32 -> fp16 conversion (one launch) ----------------
__device__ __forceinline__ void cvt4_s(const float* s, __half* d, size_t i) {
    float4 v = *(const float4*)(s + i);
    *reinterpret_cast<__half2*>(d + i)     = __halves2half2(__float2half(v.x), __float2half(v.y));
    *reinterpret_cast<__half2*>(d + i + 2) = __halves2half2(__float2half(v.z), __float2half(v.w));
}

__global__ void convert_all_kernel(
    const float* __restrict__ x,  const float* __restrict__ wg,
    const float* __restrict__ wu, const float* __restrict__ wd,
    const float* __restrict__ sg, const float* __restrict__ su,
    const float* __restrict__ sd)
{
    size_t g = (size_t)blockIdx.x * 256 + threadIdx.x;
    const size_t GB = 2097152;   // 8.39M elems / 4
    const size_t GS = 524288;    // 2.10M elems / 4
    if (g < GB) { cvt4_s(x,  g_x,  g * 4); return; }
    g -= GB;
    if (g < GB) { cvt4_s(wg, g_wg, g * 4); return; }
    g -= GB;
    if (g < GB) { cvt4_s(wu, g_wu, g * 4); return; }
    g -= GB;
    if (g < GB) { cvt4_s(wd, g_wd, g * 4); return; }
    g -= GB;
    if (g < GS) { cvt4_s(sg, g_sg, g * 4); return; }
    g -= GS;
    if (g < GS) { cvt4_s(su, g_su, g * 4); return; }
    g -= GS;
    if (g < GS) { cvt4_s(sd, g_sd, g * 4); return; }
}

// ---------------- router ----------------
__global__ void router_kernel(const float* __restrict__ x, const float* __restrict__ gw)
{
    int warp = threadIdx.x >> 5;
    int lane = threadIdx.x & 31;
    int tok  = blockIdx.x * 8 + warp;
    if (tok >= NTOK) return;
    const float* xr = x + (size_t)tok * HDIM;

    float acc[NEXP];
#pragma unroll
    for (int e = 0; e < NEXP; e++) acc[e] = 0.f;
    for (int h = lane; h < HDIM; h += 32) {
        float xv = xr[h];
#pragma unroll
        for (int e = 0; e < NEXP; e++) acc[e] += xv * gw[e * HDIM + h];
    }
#pragma unroll
    for (int e = 0; e < NEXP; e++) {
#pragma unroll
        for (int off = 16; off > 0; off >>= 1)
            acc[e] += __shfl_xor_sync(0xffffffffu, acc[e], off);
    }
    if (lane == 0) {
        float mx = acc[0];
#pragma unroll
        for (int e = 1; e < NEXP; e++) mx = fmaxf(mx, acc[e]);
        float p[NEXP]; float s = 0.f;
#pragma unroll
        for (int e = 0; e < NEXP; e++) { p[e] = expf(acc[e] - mx); s += p[e]; }
#pragma unroll
        for (int e = 0; e < NEXP; e++) p[e] /= s;
        int i0 = 0;
#pragma unroll
        for (int e = 1; e < NEXP; e++) if (p[e] > p[i0]) i0 = e;
        int i1 = -1;
#pragma unroll
        for (int e = 0; e < NEXP; e++) {
            if (e == i0) continue;
            if (i1 < 0 || p[e] > p[i1]) i1 = e;
        }
        float w0 = p[i0], w1 = p[i1];
        float inv = 1.f / (w0 + w1 + 1e-20f);
        g_topk_idx[tok * 2 + 0] = i0;
        g_topk_idx[tok * 2 + 1] = i1;
        g_topk_w[tok * 2 + 0] = w0 * inv;
        g_topk_w[tok * 2 + 1] = w1 * inv;
    }
}

// ---------------- capacity scan + compaction (reference order) ----------------
__global__ void scan_kernel()
{
    __shared__ int hist[256][NEXP];
    int t = threadIdx.x;
    const int per = (NTOK * TOPK) / 256;
    int local[NEXP];
#pragma unroll
    for (int e = 0; e < NEXP; e++) local[e] = 0;
    int base = t * per;
    for (int i = 0; i < per; i++) local[g_topk_idx[base + i]]++;
#pragma unroll
    for (int e = 0; e < NEXP; e++) hist[t][e] = local[e];
    __syncthreads();
    if (t < NEXP) {
        int run = 0;
        for (int i = 0; i < 256; i++) { int v = hist[i][t]; hist[i][t] = run; run += v; }
        g_counts[t] = run < CAP ? run : CAP;
    }
    __syncthreads();
    int off[NEXP];
#pragma unroll
    for (int e = 0; e < NEXP; e++) off[e] = hist[t][e];
    for (int i = 0; i < per; i++) {
        int slot = base + i;
        int e = g_topk_idx[slot];
        int pos = off[e]++;
        if (pos < CAP) {
            g_etok[e * CAP + pos] = slot >> 1;
            g_ewt[e * CAP + pos]  = g_topk_w[slot];
        }
    }
}

// ============================================================================
// GLU GEMM: O = silu(A@G^T)*(A@U^T) -> fp16 (single product, fp32 acc)
// CTA 128x64, BK=64, 3-stage ring, ONE sync/stage (loads issued post-barrier),
// 256 threads, 2 CTAs/SM.
// ============================================================================
#define GSTG 32768   // per stage: A 16K | G 8K | U 8K

__global__ __launch_bounds__(256, 2) void glu_f16_kernel(
    const __half* __restrict__ A_, int lda,
    const int* __restrict__ rowidx,
    const __half* __restrict__ G_, const __half* __restrict__ U_, size_t bstride,
    __half* __restrict__ O_, size_t ostride, int ldo,
    int Kdim, const int* __restrict__ counts)
{
    extern __shared__ __align__(128) char smdyn[];
    const int e = blockIdx.z;
    const int m0 = blockIdx.y * 128, n0 = blockIdx.x * 64;
    if (counts && m0 >= counts[e]) return;

    const char* Gp = (const char*)(G_ + (size_t)e * bstride);
    const char* Up = (const char*)(U_ + (size_t)e * bstride);
    __half* O = O_ + (size_t)e * ostride;
    const int* ridx = rowidx ? rowidx + e * CAP : nullptr;

    const int tid = threadIdx.x;
    uint32_t smb = (uint32_t)__cvta_generic_to_shared(smdyn);
    const int AO = 0, Go = 16384, Uo = 24576;

    int ar = tid >> 3;              // 0..31
    int ac = (tid & 7) * 16;        // 0..112
    size_t abase[4];
#pragma unroll
    for (int i = 0; i < 4; i++) {
        int row = m0 + ar + 32 * i;
        int tok = ridx ? ridx[row] : row;
        abase[i] = (size_t)tok * lda * 2 + ac;
    }
    size_t bb = (size_t)(n0 + ar) * Kdim * 2 + ac;
    const size_t bstep = (size_t)32 * Kdim * 2;
    uint32_t dA = sw128(ar * 128 + ac);
    const char* pA = (const char*)A_;

    auto load_stage = [&](int kt, int buf) {
        uint32_t s = smb + (uint32_t)buf * GSTG;
        long kb = (long)kt * 128;      // 64 halves * 2B
#pragma unroll
        for (int i = 0; i < 4; i++)
            cp16(s + AO + dA + i * 4096, pA + abase[i] + kb);
        cp16(s + Go + dA,        Gp + bb + kb);
        cp16(s + Go + dA + 4096, Gp + bb + bstep + kb);
        cp16(s + Uo + dA,        Up + bb + kb);
        cp16(s + Uo + dA + 4096, Up + bb + bstep + kb);
    };

    const int lane = tid & 31, warp = tid >> 5;
    const int wm = warp & 3, wn = warp >> 2;
    const int lr = lane & 15, lc = (lane >> 4) * 16;

    float accG[2][4][4], accU[2][4][4];
#pragma unroll
    for (int mt = 0; mt < 2; mt++)
#pragma unroll
        for (int nf = 0; nf < 4; nf++)
#pragma unroll
            for (int i = 0; i < 4; i++) { accG[mt][nf][i] = 0.f; accU[mt][nf][i] = 0.f; }

    auto comp_stage = [&](int buf) {
        uint32_t s = smb + (uint32_t)buf * GSTG;
#pragma unroll
        for (int kk = 0; kk < 4; kk++) {
            uint32_t ah[2][4];
#pragma unroll
            for (int mt = 0; mt < 2; mt++) {
                uint32_t o = sw128((wm * 32 + mt * 16 + lr) * 128 + kk * 32 + lc);
                ldsm4(ah[mt], s + AO + o);
            }
            uint32_t bg[2][4], bu[2][4];
#pragma unroll
            for (int nt = 0; nt < 2; nt++) {
                uint32_t o = sw128((wn * 32 + nt * 16 + lr) * 128 + kk * 32 + lc);
                ldsm4(bg[nt], s + Go + o);
                ldsm4(bu[nt], s + Uo + o);
            }
#pragma unroll
            for (int mt = 0; mt < 2; mt++) {
#pragma unroll
                for (int nf = 0; nf < 4; nf++) {
                    int nt = nf >> 1, f = nf & 1;
                    mma_f16(accG[mt][nf], ah[mt], bg[nt][f], bg[nt][f + 2]);
                    mma_f16(accU[mt][nf], ah[mt], bu[nt][f], bu[nt][f + 2]);
                }
            }
        }
    };

    // ---- 3-stage pipeline, single sync/stage; loads issued AFTER the barrier.
    // Safety: a warp issuing load(kt+2) passed sync(kt), which all warps reach
    // only after comp(kt-1); the only concurrent reader is comp(kt) on buffer
    // kt%3, and (kt+2)%3 != kt%3.
    const int KT = Kdim >> 6;
    load_stage(0, 0); CP_COMMIT();
    load_stage(1, 1); CP_COMMIT();
    for (int kt = 0; kt < KT; kt++) {
        if (kt + 1 < KT) { CP_WAIT1(); } else { CP_WAIT0(); }
        __syncthreads();
        if (kt + 2 < KT) { load_stage(kt + 2, (kt + 2) % 3); CP_COMMIT(); }
        comp_stage(kt % 3);
    }

    int r0e = m0 + wm * 32 + (lane >> 2);
    int c0e = n0 + wn * 32 + (lane & 3) * 2;
#pragma unroll
    for (int mt = 0; mt < 2; mt++) {
#pragma unroll
        for (int nf = 0; nf < 4; nf++) {
            int r = r0e + mt * 16;
            int c = c0e + nf * 8;
            float v0 = silu_f(accG[mt][nf][0]) * accU[mt][nf][0];
            float v1 = silu_f(accG[mt][nf][1]) * accU[mt][nf][1];
            float v2 = silu_f(accG[mt][nf][2]) * accU[mt][nf][2];
            float v3 = silu_f(accG[mt][nf][3]) * accU[mt][nf][3];
            *reinterpret_cast<__half2*>(O + (size_t)r * ldo + c) =
                __halves2half2(__float2half(v0), __float2half(v1));
            *reinterpret_cast<__half2*>(O + (size_t)(r + 8) * ldo + c) =
                __halves2half2(__float2half(v2), __float2half(v3));
        }
    }
}

// ============================================================================
// Down GEMM: out[tok,n] (+)= w * (A@B^T), fp16 x fp16, fp32 acc/out
// CTA 128x128, BK=64, warp grid 4x2 (warp tile 32x64), 3-stage ring,
// ONE sync/stage, 256 threads, 2 CTAs/SM.
// ============================================================================
#define DSTG 32768   // per stage: A 16K | B 16K

__global__ __launch_bounds__(256, 2) void down_f16_kernel(
    const __half* __restrict__ A_, int lda, size_t astride,
    const __half* __restrict__ B_, size_t bstride,
    const int* __restrict__ rowidx, const float* __restrict__ wts,
    const int* __restrict__ counts, int Mtotal,
    float* __restrict__ out, int ldo, int Kdim, int accumulate)
{
    extern __shared__ __align__(128) char smdyn[];
    const int e = blockIdx.z;
    const int m0 = blockIdx.y * 128, n0 = blockIdx.x * 128;
    if (counts && m0 >= counts[e]) return;

    const char* pA = (const char*)(A_ + (size_t)e * astride);
    const char* pB = (const char*)(B_ + (size_t)e * bstride);

    const int tid = threadIdx.x;
    uint32_t smb = (uint32_t)__cvta_generic_to_shared(smdyn);
    const int AO = 0, BO = 16384;

    int ar = tid >> 3;              // 0..31
    int ac = (tid & 7) * 16;
    size_t ab = (size_t)(m0 + ar) * lda * 2 + ac;
    const size_t astep = (size_t)32 * lda * 2;
    size_t bb = (size_t)(n0 + ar) * Kdim * 2 + ac;
    const size_t bstep = (size_t)32 * Kdim * 2;
    uint32_t dA = sw128(ar * 128 + ac);

    auto load_stage = [&](int kt, int buf) {
        uint32_t s = smb + (uint32_t)buf * DSTG;
        long kb = (long)kt * 128;
#pragma unroll
        for (int i = 0; i < 4; i++) {
            cp16(s + AO + dA + i * 4096, pA + ab + (size_t)i * astep + kb);
            cp16(s + BO + dA + i * 4096, pB + bb + (size_t)i * bstep + kb);
        }
    };

    const int lane = tid & 31, warp = tid >> 5;
    const int wm = warp & 3, wn = warp >> 2;   // wm 0..3 (M), wn 0..1 (N)
    const int lr = lane & 15, lc = (lane >> 4) * 16;

    float acc[2][8][4];
#pragma unroll
    for (int mt = 0; mt < 2; mt++)
#pragma unroll
        for (int nf = 0; nf < 8; nf++)
#pragma unroll
            for (int i = 0; i < 4; i++) acc[mt][nf][i] = 0.f;

    auto comp_stage = [&](int buf) {
        uint32_t s = smb + (uint32_t)buf * DSTG;
#pragma unroll
        for (int kk = 0; kk < 4; kk++) {
            uint32_t ah[2][4];
#pragma unroll
            for (int mt = 0; mt < 2; mt++) {
                uint32_t o = sw128((wm * 32 + mt * 16 + lr) * 128 + kk * 32 + lc);
                ldsm4(ah[mt], s + AO + o);
            }
            uint32_t bh[4][4];
#pragma unroll
            for (int nt = 0; nt < 4; nt++) {
                uint32_t o = sw128((wn * 64 + nt * 16 + lr) * 128 + kk * 32 + lc);
                ldsm4(bh[nt], s + BO + o);
            }
#pragma unroll
            for (int mt = 0; mt < 2; mt++) {
#pragma unroll
                for (int nf = 0; nf < 8; nf++) {
                    int nt = nf >> 1, f = nf & 1;
                    mma_f16(acc[mt][nf], ah[mt], bh[nt][f], bh[nt][f + 2]);
                }
            }
        }
    };

    const int KT = Kdim >> 6;
    load_stage(0, 0); CP_COMMIT();
    load_stage(1, 1); CP_COMMIT();
    for (int kt = 0; kt < KT; kt++) {
        if (kt + 1 < KT) { CP_WAIT1(); } else { CP_WAIT0(); }
        __syncthreads();
        if (kt + 2 < KT) { load_stage(kt + 2, (kt + 2) % 3); CP_COMMIT(); }
        comp_stage(kt % 3);
    }

    int Mv = counts ? counts[e] : Mtotal;
#pragma unroll
    for (int mt = 0; mt < 2; mt++) {
#pragma unroll
        for (int half = 0; half < 2; half++) {
            int r = m0 + wm * 32 + mt * 16 + (lane >> 2) + half * 8;
            if (r >= Mv) continue;
            int tok = r; float w = 1.f;
            if (rowidx) { tok = rowidx[e * CAP + r]; w = wts[e * CAP + r]; }
            float* orow = out + (size_t)tok * ldo;
#pragma unroll
            for (int nf = 0; nf < 8; nf++) {
                int c = n0 + wn * 64 + nf * 8 + (lane & 3) * 2;
                float v0 = acc[mt][nf][half * 2 + 0] * w;
                float v1 = acc[mt][nf][half * 2 + 1] * w;
                if (accumulate) {
                    atomicAdd(&orow[c],     v0);
                    atomicAdd(&orow[c + 1], v1);
                } else {
                    orow[c]     = v0;
                    orow[c + 1] = v1;
                }
            }
        }
    }
}

// ---------------- launch ----------------
extern "C" void kernel_launch(void* const* d_in, const int* in_sizes, int n_in,
                              void* d_out, int out_size)
{
    const float* x       = (const float*)d_in[0];
    const float* gate_w  = (const float*)d_in[1];
    const float* we_gate = (const float*)d_in[2];
    const float* we_up   = (const float*)d_in[3];
    const float* we_down = (const float*)d_in[4];
    const float* ws_gate = (const float*)d_in[5];
    const float* ws_up   = (const float*)d_in[6];
    const float* ws_down = (const float*)d_in[7];
    float* out = (float*)d_out;

    cudaFuncSetAttribute(glu_f16_kernel,  cudaFuncAttributeMaxDynamicSharedMemorySize, 3 * GSTG);
    cudaFuncSetAttribute(down_f16_kernel, cudaFuncAttributeMaxDynamicSharedMemorySize, 3 * DSTG);

    __half *xh, *wg, *wu, *wd, *sg, *su, *sd, *ar, *as;
    int *etok, *counts; float *ewt;
    cudaGetSymbolAddress((void**)&xh, g_x);
    cudaGetSymbolAddress((void**)&wg, g_wg);   cudaGetSymbolAddress((void**)&wu, g_wu);
    cudaGetSymbolAddress((void**)&wd, g_wd);
    cudaGetSymbolAddress((void**)&sg, g_sg);   cudaGetSymbolAddress((void**)&su, g_su);
    cudaGetSymbolAddress((void**)&sd, g_sd);
    cudaGetSymbolAddress((void**)&ar, g_ar);   cudaGetSymbolAddress((void**)&as, g_as);
    cudaGetSymbolAddress((void**)&etok, g_etok);
    cudaGetSymbolAddress((void**)&ewt,  g_ewt);
    cudaGetSymbolAddress((void**)&counts, g_counts);

    // 1: fused conversion
    convert_all_kernel<<<38912, 256>>>(x, we_gate, we_up, we_down, ws_gate, ws_up, ws_down);
    // 2, 3: router + capacity scan
    router_kernel<<<NTOK / 8, 256>>>(x, gate_w);
    scan_kernel<<<1, 256>>>();

    // 4: shared gate/up + SwiGLU -> g_as
    glu_f16_kernel<<<dim3(SHI / 64, NTOK / 128, 1), 256, 3 * GSTG>>>(
        xh, HDIM, nullptr,
        sg, su, 0,
        as, 0, SHI, HDIM, nullptr);

    // 5: shared down-proj (initializes poisoned out)
    down_f16_kernel<<<dim3(HDIM / 128, NTOK / 128, 1), 256, 3 * DSTG>>>(
        as, SHI, 0,
        sd, 0,
        nullptr, nullptr, nullptr, NTOK,
        out, HDIM, SHI, /*accumulate=*/0);

    // 6 (ncu capture slot): routed gate/up + SwiGLU -> g_ar
    glu_f16_kernel<<<dim3(IDIM / 64, CAP / 128, NEXP), 256, 3 * GSTG>>>(
        xh, HDIM, etok,
        wg, wu, (size_t)IDIM * HDIM,
        ar, (size_t)CAP * IDIM, IDIM, HDIM, counts);

    // 7: routed down-proj, weighted atomic scatter
    down_f16_kernel<<<dim3(HDIM / 128, CAP / 128, NEXP), 256, 3 * DSTG>>>(
        ar, IDIM, (size_t)CAP * IDIM,
        wd, (size_t)HDIM * IDIM,
        etok, ewt, counts, 0,
        out, HDIM, IDIM, /*accumulate=*/1);
}